// round 13
// baseline (speedup 1.0000x reference)
#include <cuda_runtime.h>
#include <cstdint>
#include <cstddef>

// Problem constants (reference: N=50000, D=128, E=800000, A=5)
#define NMAX 50000
#define DD 128
#define AA 5
#define HH 64
#define BN 64    // nodes per block in k_nodeA
#define NT 128   // threads per block in k_nodeA (2 threads per node)

// ---------------- scratch (static device globals; zero-init at module load) --
// Invariant: g_deg and g_B4 are zero at entry of every kernel_launch call:
// load-time zero covers the first call; k_nodeA re-zeroes g_B4 (before k_edge
// accumulates) and k_final re-zeroes g_deg at tile-staging time (each node's
// deg is read only by its own tile's block).
__device__ __align__(16) float g_B4 [NMAX*4];  // edge softmax sums (4 comps)
__device__ __align__(16) float g_xs8[NMAX*8];  // x @ w[:, :128]^T + bias (pad)
__device__ __align__(16) float g_xd8[NMAX*8];  // x @ w[:, 128:]^T (pad)
__device__ __align__(16) float g_aw8[NMAX*8];  // attention softmax (pad)
__device__ __align__(16) float g_h  [NMAX*HH]; // relu(topo @ t1_w^T + t1_b)
__device__ int   g_deg[NMAX];
__device__ int   g_degmax;                     // monotone max; stable across replays

// ---------------- f32x2 packed math helpers ----------------------------------
__device__ __forceinline__ unsigned long long pack2(float v) {
    unsigned long long r;
    asm("mov.b64 %0, {%1, %1};" : "=l"(r) : "f"(v));
    return r;
}
__device__ __forceinline__ unsigned long long packf2(float x, float y) {
    unsigned long long r;
    asm("mov.b64 %0, {%1, %2};" : "=l"(r) : "f"(x), "f"(y));
    return r;
}
__device__ __forceinline__ unsigned long long mul2(unsigned long long a,
                                                   unsigned long long b) {
    unsigned long long d;
    asm("mul.rn.f32x2 %0, %1, %2;" : "=l"(d) : "l"(a), "l"(b));
    return d;
}
__device__ __forceinline__ unsigned long long fma2(unsigned long long a,
                                                   unsigned long long b,
                                                   unsigned long long c) {
    unsigned long long d;
    asm("fma.rn.f32x2 %0, %1, %2, %3;" : "=l"(d) : "l"(a), "l"(b), "l"(c));
    return d;
}
__device__ __forceinline__ void unpack2(unsigned long long v, float& x, float& y) {
    asm("mov.b64 {%0, %1}, %2;" : "=f"(x), "=f"(y) : "l"(v));
}
// vectorized float4 reduction (PTX ISA 8.1+, sm_90+)
__device__ __forceinline__ void red_add_v4(float* p, float b0, float b1,
                                           float b2, float b3) {
    asm volatile(
        "{\n\t.reg .u64 pg;\n\t"
        "cvta.to.global.u64 pg, %0;\n\t"
        "red.global.add.v4.f32 [pg], {%1, %2, %3, %4};\n\t}"
        :: "l"(p), "f"(b0), "f"(b1), "f"(b2), "f"(b3) : "memory");
}

// ---------------- per-warp int64/int32 edge-index detection ------------------
__device__ __forceinline__ int detect_is64(const void* ei) {
    unsigned hi = ((const unsigned*)ei)[2 * (threadIdx.x & 31) + 1];
    return !__any_sync(0xffffffffu, hi != 0u);
}

// ---------------- Threefry-2x32 (JAX partitionable semantics) ----------------
__host__ __device__ constexpr unsigned rotl32(unsigned v, int s) {
    return (v << s) | (v >> (32 - s));
}
struct TFout { unsigned a, b; };
__host__ __device__ constexpr TFout tf2x32(unsigned k0, unsigned k1,
                                           unsigned x0, unsigned x1) {
    unsigned ks[3] = {k0, k1, k0 ^ k1 ^ 0x1BD11BDAu};
    const int R0[4] = {13, 15, 26, 6};
    const int R1[4] = {17, 29, 16, 24};
    x0 += ks[0]; x1 += ks[1];
    for (int i = 0; i < 5; i++) {
        for (int j = 0; j < 4; j++) {
            int r = (i % 2 == 0) ? R0[j] : R1[j];
            x0 += x1; x1 = rotl32(x1, r); x1 ^= x0;
        }
        x0 += ks[(i + 1) % 3];
        x1 += ks[(i + 2) % 3] + (unsigned)(i + 1);
    }
    return {x0, x1};
}
constexpr TFout KEY1 = tf2x32(0u, 42u, 0u, 0u);
constexpr TFout KEY2 = tf2x32(0u, 42u, 0u, 1u);

__device__ __forceinline__ float jax_uniform01(unsigned key0, unsigned key1,
                                               unsigned n) {
    TFout r = tf2x32(key0, key1, 0u, n);
    unsigned bits = r.a ^ r.b;
    return __uint_as_float(0x3F800000u | (bits >> 9)) - 1.0f;
}

// ---------------- edge index loader -------------------------------------------
__device__ __forceinline__ int ld_edge(const void* ei, long long pos, int is64) {
    return is64 ? (int)__ldg(((const long long*)ei) + pos)
                : __ldg(((const int*)ei) + pos);
}

// ---------------- K1: degree histogram over src + fused max ------------------
__global__ void __launch_bounds__(256)
k_degree(const void* __restrict__ ei, long long E) {
    int tid = threadIdx.x;
    int is64 = detect_is64(ei);
    long long e = (long long)blockIdx.x * 256 + tid;
    int cand = 0;
    if (e < E) {
        int s = ld_edge(ei, e, is64);
        cand = atomicAdd(&g_deg[s], 1) + 1;
    }
#pragma unroll
    for (int o = 16; o; o >>= 1)
        cand = max(cand, __shfl_xor_sync(0xffffffffu, cand, o));
    __shared__ int sm[8];
    if ((tid & 31) == 0) sm[tid >> 5] = cand;
    __syncthreads();
    if (tid < 8) {
        int t = sm[tid];
#pragma unroll
        for (int o = 4; o; o >>= 1) t = max(t, __shfl_xor_sync(0xffu, t, o));
        if (tid == 0) atomicMax(&g_degmax, t);
    }
}

// ---------------- K2: per-node precompute (2 threads per node) ----------------
__global__ void __launch_bounds__(NT)
k_nodeA(const float* __restrict__ x,
        const float* __restrict__ attn_w, const float* __restrict__ attn_b,
        const float* __restrict__ w_w,  const float* __restrict__ w_b,
        const float* __restrict__ t1w,  const float* __restrict__ t1b,
        int N, float Ef) {
    __shared__ float  s_x[BN * 33];      // 8.4 KB, conflict-free layout
    __shared__ float4 s_attn[AA * 32];   // [5][128]
    __shared__ float4 s_w[AA * 64];      // [5][256]
    __shared__ float4 s_t1wT[AA * 16];   // transposed [5][64]
    __shared__ float4 s_t1b4[16];
    __shared__ float  s_ab[AA], s_wb[AA];
    int tid = threadIdx.x;
    for (int i = tid; i < AA * 32; i += NT) s_attn[i] = ((const float4*)attn_w)[i];
    for (int i = tid; i < AA * 64; i += NT) s_w[i]    = ((const float4*)w_w)[i];
    for (int idx = tid; idx < AA * HH; idx += NT) {
        int i = idx / HH, j = idx % HH;                // t1w is [64][5]
        ((float*)s_t1wT)[i * HH + j] = t1w[j * AA + i];
    }
    for (int i = tid; i < 16; i += NT) s_t1b4[i] = ((const float4*)t1b)[i];
    if (tid < AA) { s_ab[tid] = attn_b[tid]; s_wb[tid] = w_b[tid]; }
    __syncthreads();

    int nbase = blockIdx.x * BN;
    int r = tid >> 1, h = tid & 1;
    int n = nbase + r;

    float pa[AA], ps[AA], pd[AA];
#pragma unroll
    for (int k = 0; k < AA; k++) { pa[k] = 0.f; ps[k] = 0.f; pd[k] = 0.f; }

    const float4* xg = (const float4*)x;
#pragma unroll
    for (int ch = 0; ch < 4; ch++) {
        if (ch) __syncthreads();
#pragma unroll
        for (int it = 0; it < 4; it++) {
            int idx = it * NT + tid;
            int rr = idx >> 3, c = idx & 7;
            int gn = nbase + rr;
            float4 v = make_float4(0.f, 0.f, 0.f, 0.f);
            if (gn < N) v = __ldg(xg + (size_t)gn * 32 + ch * 8 + c);
            float* p = s_x + rr * 33 + c * 4;
            p[0] = v.x; p[1] = v.y; p[2] = v.z; p[3] = v.w;
        }
        __syncthreads();
        const float* xr = s_x + r * 33 + h * 16;
#pragma unroll
        for (int j = 0; j < 4; j++) {
            float x0 = xr[j*4+0], x1 = xr[j*4+1];
            float x2 = xr[j*4+2], x3 = xr[j*4+3];
            int c = ch * 8 + h * 4 + j;   // halves 16 banks apart: dual-bcast
#pragma unroll
            for (int k = 0; k < AA; k++) {
                float4 av = s_attn[k * 32 + c];
                pa[k] += x0*av.x + x1*av.y + x2*av.z + x3*av.w;
                float4 sv = s_w[k * 64 + c];
                ps[k] += x0*sv.x + x1*sv.y + x2*sv.z + x3*sv.w;
                float4 dv = s_w[k * 64 + 32 + c];
                pd[k] += x0*dv.x + x1*dv.y + x2*dv.z + x3*dv.w;
            }
        }
    }
#pragma unroll
    for (int k = 0; k < AA; k++) {
        pa[k] += __shfl_xor_sync(0xffffffffu, pa[k], 1);
        ps[k] += __shfl_xor_sync(0xffffffffu, ps[k], 1);
        pd[k] += __shfl_xor_sync(0xffffffffu, pd[k], 1);
    }
#pragma unroll
    for (int k = 0; k < AA; k++) { pa[k] += s_ab[k]; ps[k] += s_wb[k]; }

    float m = pa[0];
#pragma unroll
    for (int k = 1; k < AA; k++) m = fmaxf(m, pa[k]);
    float ev[AA], sum = 0.f;
#pragma unroll
    for (int k = 0; k < AA; k++) { ev[k] = __expf(pa[k] - m); sum += ev[k]; }
    float inv = __fdividef(1.0f, sum);

    bool ok = (n < N);
    if (ok && h == 0) {
        *(float4*)(g_aw8 + (size_t)n * 8) =
            make_float4(ev[0]*inv, ev[1]*inv, ev[2]*inv, ev[3]*inv);
        g_aw8[(size_t)n * 8 + 4] = ev[4] * inv;
        *(float4*)(g_xs8 + (size_t)n * 8) = make_float4(ps[0], ps[1], ps[2], ps[3]);
        g_xs8[(size_t)n * 8 + 4] = ps[4];
    }
    if (ok && h == 1) {
        *(float4*)(g_xd8 + (size_t)n * 8) = make_float4(pd[0], pd[1], pd[2], pd[3]);
        g_xd8[(size_t)n * 8 + 4] = pd[4];
        // re-zero this node's B4 accumulator for the upcoming k_edge pass
        *(float4*)(g_B4 + (size_t)n * 4) = make_float4(0.f, 0.f, 0.f, 0.f);
    }

    // topology features + hidden layer
    int nc = (n < N) ? n : (N - 1);
    float deg   = (float)__ldg(&g_deg[nc]);
    float dmaxf = (float)g_degmax;
    float meanf = Ef / (float)N;
    unsigned kk0 = h ? KEY2.a : KEY1.a;
    unsigned kk1 = h ? KEY2.b : KEY1.b;
    float u_own   = jax_uniform01(kk0, kk1, (unsigned)n);
    float u_other = __shfl_xor_sync(0xffffffffu, u_own, 1);
    float u1 = h ? u_other : u_own;   // KEY1 stream
    float u2 = h ? u_own   : u_other; // KEY2 stream

    float tv[5];
    tv[0] = deg / (dmaxf + 1e-6f);
    tv[1] = u1 * 0.5f + 0.25f;
    tv[2] = deg / (Ef + 1e-6f);
    tv[3] = 1.0f / (1.0f + __expf(-(deg - meanf)));
    tv[4] = u2;

    if (ok) {
        float4* hout = (float4*)(g_h + (size_t)n * HH);
#pragma unroll
        for (int jc = 0; jc < 8; jc++) {
            int jc4 = h * 8 + jc;
            float4 hv = s_t1b4[jc4];
#pragma unroll
            for (int i = 0; i < AA; i++) {
                float4 wv = s_t1wT[i * 16 + jc4];
                hv.x += tv[i] * wv.x; hv.y += tv[i] * wv.y;
                hv.z += tv[i] * wv.z; hv.w += tv[i] * wv.w;
            }
            hv.x = fmaxf(hv.x, 0.f); hv.y = fmaxf(hv.y, 0.f);
            hv.z = fmaxf(hv.z, 0.f); hv.w = fmaxf(hv.w, 0.f);
            hout[jc4] = hv;
        }
    }
}

// ---------------- K3: edge kernel — thread-per-edge softmax, f32x2 store -----
__global__ void __launch_bounds__(256)
k_edge(const void* __restrict__ ei, long long E,
       const float* __restrict__ anchor, float* __restrict__ outE) {
    __shared__ unsigned long long s_bp[5][256];   // packed (b,b), column-major
    int tid  = threadIdx.x;
    int lane = tid & 31;
    int warp = tid >> 5;
    int is64 = detect_is64(ei);

    unsigned long long alo[AA], ahi[AA];
#pragma unroll
    for (int k = 0; k < AA; k++) {
        float4 a = __ldg(((const float4*)anchor) + k * 32 + lane);
        alo[k] = packf2(a.x, a.y);
        ahi[k] = packf2(a.z, a.w);
    }

    long long e = (long long)blockIdx.x * 256 + tid;
    if (e < E) {
        int src = ld_edge(ei, e, is64);
        int dst = ld_edge(ei, E + e, is64);
        float4 s4 = __ldg((const float4*)(g_xs8 + (size_t)src * 8));
        float  s5 = __ldg(g_xs8 + (size_t)src * 8 + 4);
        float4 d4 = __ldg((const float4*)(g_xd8 + (size_t)dst * 8));
        float  d5 = __ldg(g_xd8 + (size_t)dst * 8 + 4);
        float l[5];
        l[0] = s4.x + d4.x; l[1] = s4.y + d4.y; l[2] = s4.z + d4.z;
        l[3] = s4.w + d4.w; l[4] = s5 + d5;
#pragma unroll
        for (int k = 0; k < 5; k++) l[k] = fmaxf(l[k], 0.01f * l[k]); // leaky
        float m = l[0];
#pragma unroll
        for (int k = 1; k < 5; k++) m = fmaxf(m, l[k]);
        float ev[5], sum = 0.f;
#pragma unroll
        for (int k = 0; k < 5; k++) { ev[k] = __expf(l[k] - m); sum += ev[k]; }
        float inv = __fdividef(1.0f, sum);
        float b[5];
#pragma unroll
        for (int k = 0; k < 5; k++) b[k] = ev[k] * inv;
        red_add_v4(g_B4 + (size_t)src * 4, b[0], b[1], b[2], b[3]);
#pragma unroll
        for (int k = 0; k < 5; k++) s_bp[k][tid] = pack2(b[k]);  // conflict-free
    }
    __syncwarp();

    long long base = (long long)blockIdx.x * 256 + warp * 32;
    float4* o4 = (float4*)outE;
    int nfull = (base + 32 <= E) ? 32 : (int)(E > base ? E - base : 0);
    if (nfull == 32) {
#pragma unroll 4
        for (int j = 0; j < 32; j++) {
            int sb = warp * 32 + j;                    // uniform -> broadcast
            unsigned long long p0 = s_bp[0][sb], p1 = s_bp[1][sb],
                               p2 = s_bp[2][sb], p3 = s_bp[3][sb],
                               p4 = s_bp[4][sb];
            unsigned long long lo = mul2(p0, alo[0]);
            lo = fma2(p1, alo[1], lo); lo = fma2(p2, alo[2], lo);
            lo = fma2(p3, alo[3], lo); lo = fma2(p4, alo[4], lo);
            unsigned long long hi = mul2(p0, ahi[0]);
            hi = fma2(p1, ahi[1], hi); hi = fma2(p2, ahi[2], hi);
            hi = fma2(p3, ahi[3], hi); hi = fma2(p4, ahi[4], hi);
            float4 o;
            unpack2(lo, o.x, o.y);
            unpack2(hi, o.z, o.w);
            __stcs(o4 + (size_t)(base + j) * 32 + lane, o);
        }
    } else {
        for (int j = 0; j < nfull; j++) {
            int sb = warp * 32 + j;
            unsigned long long p0 = s_bp[0][sb], p1 = s_bp[1][sb],
                               p2 = s_bp[2][sb], p3 = s_bp[3][sb],
                               p4 = s_bp[4][sb];
            unsigned long long lo = mul2(p0, alo[0]);
            lo = fma2(p1, alo[1], lo); lo = fma2(p2, alo[2], lo);
            lo = fma2(p3, alo[3], lo); lo = fma2(p4, alo[4], lo);
            unsigned long long hi = mul2(p0, ahi[0]);
            hi = fma2(p1, ahi[1], hi); hi = fma2(p2, ahi[2], hi);
            hi = fma2(p3, ahi[3], hi); hi = fma2(p4, ahi[4], hi);
            float4 o;
            unpack2(lo, o.x, o.y);
            unpack2(hi, o.z, o.w);
            __stcs(o4 + (size_t)(base + j) * 32 + lane, o);
        }
    }
}

// ---------------- K4: final per-node (smem-staged h, f32x2 GEMM) --------------
// Block processes tiles of 32 nodes. h rows staged coalesced into smem once;
// compute reads them via broadcast LDS (29cyc) instead of serialized L2 loads.
// g_deg is staged+re-zeroed here (only this block reads these nodes' deg).
__global__ void __launch_bounds__(256)
k_final(const float* __restrict__ x,
        const float* __restrict__ node_anchor, const float* __restrict__ anchor,
        const float* __restrict__ t2w, const float* __restrict__ t2b,
        float* __restrict__ outF, int N) {
    __shared__ float4 s_h4[32 * 16];   // 32 nodes x 64 floats (8 KB)
    __shared__ float4 s_B[32];
    __shared__ float4 s_aw[32];
    __shared__ float  s_aw5[32];
    __shared__ float  s_degf[32];

    int tid  = threadIdx.x;
    int lane = tid & 31;
    int warp = tid >> 5;
    int half = warp >> 2;          // 0: nodes 0-15, 1: nodes 16-31
    int cg   = warp & 3;
    int col  = cg * 32 + lane;

    // t2_w row for this column, packed as 32 (w[2j], w[2j+1]) f32x2 pairs
    unsigned long long wp[32];
#pragma unroll
    for (int j4 = 0; j4 < 16; j4++) {
        float4 wv = ((const float4*)t2w)[(size_t)col * 16 + j4];
        wp[2*j4+0] = packf2(wv.x, wv.y);
        wp[2*j4+1] = packf2(wv.z, wv.w);
    }
    float areg[AA], nareg[AA];
#pragma unroll
    for (int k = 0; k < AA; k++) {
        areg[k]  = __ldg(&anchor[k * DD + col]);
        nareg[k] = __ldg(&node_anchor[k * DD + col]);
    }
    float bias = __ldg(&t2b[col]);

    int ntiles = (N + 31) >> 5;
    for (int tile = blockIdx.x; tile < ntiles; tile += gridDim.x) {
        int nb = tile << 5;
        __syncthreads();                 // protect smem reuse across tiles
        // ---- stage 32 h rows, coalesced (2 float4 per thread, MLP-deep) ----
#pragma unroll
        for (int k = 0; k < 2; k++) {
            int idx = k * 256 + tid;
            int row = idx >> 4, c = idx & 15;
            int gn = nb + row;
            float4 v = make_float4(0.f, 0.f, 0.f, 0.f);
            if (gn < N) v = __ldg(((const float4*)g_h) + (size_t)gn * 16 + c);
            s_h4[idx] = v;
        }
        if (tid < 32) {
            int gn = nb + tid;
            if (gn < N) {
                s_B[tid]    = *(const float4*)(g_B4 + (size_t)gn * 4);
                s_aw[tid]   = *(const float4*)(g_aw8 + (size_t)gn * 8);
                s_aw5[tid]  = g_aw8[(size_t)gn * 8 + 4];
                s_degf[tid] = (float)g_deg[gn];
                g_deg[gn]   = 0;   // re-zero for next graph replay
            }
        }
        __syncthreads();
        // ---- compute: each warp does 16 nodes x its 32 columns ----
#pragma unroll 2
        for (int j = 0; j < 16; j++) {
            int nl = half * 16 + j;
            int gn = nb + nl;
            if (gn >= N) break;
            float xv = x[(size_t)gn * DD + col];          // coalesced, L2
            const ulonglong2* hrow = (const ulonglong2*)(s_h4 + nl * 16);
            unsigned long long a0 = 0ULL, a1 = 0ULL, a2 = 0ULL, a3 = 0ULL;
#pragma unroll
            for (int q = 0; q < 4; q++) {                 // broadcast LDS.128
                ulonglong2 hA = hrow[q*4+0], hB = hrow[q*4+1],
                           hC = hrow[q*4+2], hD = hrow[q*4+3];
                a0 = fma2(hA.x, wp[8*q+0], a0);
                a1 = fma2(hA.y, wp[8*q+1], a1);
                a2 = fma2(hB.x, wp[8*q+2], a2);
                a3 = fma2(hB.y, wp[8*q+3], a3);
                a0 = fma2(hC.x, wp[8*q+4], a0);
                a1 = fma2(hC.y, wp[8*q+5], a1);
                a2 = fma2(hD.x, wp[8*q+6], a2);
                a3 = fma2(hD.y, wp[8*q+7], a3);
            }
            a0 = fma2(a1, pack2(1.0f), a0);
            a2 = fma2(a3, pack2(1.0f), a2);
            float s0, s1, s2, s3;
            unpack2(a0, s0, s1);
            unpack2(a2, s2, s3);
            float acc = bias + ((s0 + s1) + (s2 + s3));

            float4 B   = s_B[nl];                         // broadcast LDS
            float deg  = s_degf[nl];
            float4 aw4 = s_aw[nl];
            float aw5  = s_aw5[nl];
            float B4v  = deg - B.x - B.y - B.z - B.w;
            float agg  = B.x*areg[0] + B.y*areg[1] + B.z*areg[2] + B.w*areg[3]
                       + B4v*areg[4];
            float np   = aw4.x*nareg[0] + aw4.y*nareg[1] + aw4.z*nareg[2]
                       + aw4.w*nareg[3] + aw5*nareg[4];
            outF[(size_t)gn * DD + col] = xv + np + acc * agg;
        }
    }
}

// ---------------- launch ------------------------------------------------------
extern "C" void kernel_launch(void* const* d_in, const int* in_sizes, int n_in,
                              void* d_out, int out_size) {
    const float* x           = (const float*)d_in[0];
    const void*  ei          = d_in[1];
    const float* anchor      = (const float*)d_in[3];
    const float* w_w         = (const float*)d_in[4];
    const float* w_b         = (const float*)d_in[5];
    const float* node_anchor = (const float*)d_in[6];
    const float* attn_w      = (const float*)d_in[7];
    const float* attn_b      = (const float*)d_in[8];
    const float* t1w         = (const float*)d_in[9];
    const float* t1b         = (const float*)d_in[10];
    const float* t2w         = (const float*)d_in[11];
    const float* t2b         = (const float*)d_in[12];

    int       N  = in_sizes[0] / DD;
    long long E  = (long long)in_sizes[1] / 2;
    float     Ef = (float)E;

    float* outF = (float*)d_out;                  // final_x [N, D]
    float* outE = outF + (size_t)N * DD;          // edge_prompt [E, D]

    k_degree<<<(unsigned)((E + 255) / 256), 256>>>(ei, E);
    k_nodeA <<<(N + BN - 1) / BN, NT>>>(x, attn_w, attn_b, w_w, w_b,
                                        t1w, t1b, N, Ef);
    k_edge  <<<(unsigned)((E + 255) / 256), 256>>>(ei, E, anchor, outE);
    k_final <<<592, 256>>>(x, node_anchor, anchor, t2w, t2b, outF, N);
}

// round 14
// speedup vs baseline: 1.3554x; 1.3554x over previous
#include <cuda_runtime.h>
#include <cstdint>
#include <cstddef>

// Problem constants (reference: N=50000, D=128, E=800000, A=5)
#define NMAX 50000
#define DD 128
#define AA 5
#define HH 64
#define BN 64    // nodes per block in k_nodeA
#define NT 128   // threads per block in k_nodeA (2 threads per node)

// ---------------- scratch (static device globals; zero-init at module load) --
// Invariant: g_deg and g_B4 are zero at entry of every kernel_launch call:
// load-time zero covers the first call; k_nodeA re-zeroes g_B4 (before k_edge
// accumulates) and k_final re-zeroes g_deg at tile-staging time (each node's
// deg is read only by its own tile's block).
__device__ __align__(16) float g_B4 [NMAX*4];  // edge softmax sums (4 comps)
__device__ __align__(16) float g_xs8[NMAX*8];  // x @ w[:, :128]^T + bias (pad)
__device__ __align__(16) float g_xd8[NMAX*8];  // x @ w[:, 128:]^T (pad)
__device__ __align__(16) float g_aw8[NMAX*8];  // attention softmax (pad)
__device__ __align__(16) float g_h  [NMAX*HH]; // relu(topo @ t1_w^T + t1_b)
__device__ int   g_deg[NMAX];
__device__ int   g_degmax;                     // monotone max; stable across replays

// ---------------- f32x2 packed math helpers ----------------------------------
__device__ __forceinline__ unsigned long long pack2(float v) {
    unsigned long long r;
    asm("mov.b64 %0, {%1, %1};" : "=l"(r) : "f"(v));
    return r;
}
__device__ __forceinline__ unsigned long long packf2(float x, float y) {
    unsigned long long r;
    asm("mov.b64 %0, {%1, %2};" : "=l"(r) : "f"(x), "f"(y));
    return r;
}
__device__ __forceinline__ unsigned long long mul2(unsigned long long a,
                                                   unsigned long long b) {
    unsigned long long d;
    asm("mul.rn.f32x2 %0, %1, %2;" : "=l"(d) : "l"(a), "l"(b));
    return d;
}
__device__ __forceinline__ unsigned long long fma2(unsigned long long a,
                                                   unsigned long long b,
                                                   unsigned long long c) {
    unsigned long long d;
    asm("fma.rn.f32x2 %0, %1, %2, %3;" : "=l"(d) : "l"(a), "l"(b), "l"(c));
    return d;
}
__device__ __forceinline__ void unpack2(unsigned long long v, float& x, float& y) {
    asm("mov.b64 {%0, %1}, %2;" : "=f"(x), "=f"(y) : "l"(v));
}
// vectorized float4 reduction (PTX ISA 8.1+, sm_90+)
__device__ __forceinline__ void red_add_v4(float* p, float b0, float b1,
                                           float b2, float b3) {
    asm volatile(
        "{\n\t.reg .u64 pg;\n\t"
        "cvta.to.global.u64 pg, %0;\n\t"
        "red.global.add.v4.f32 [pg], {%1, %2, %3, %4};\n\t}"
        :: "l"(p), "f"(b0), "f"(b1), "f"(b2), "f"(b3) : "memory");
}

// ---------------- per-warp int64/int32 edge-index detection ------------------
__device__ __forceinline__ int detect_is64(const void* ei) {
    unsigned hi = ((const unsigned*)ei)[2 * (threadIdx.x & 31) + 1];
    return !__any_sync(0xffffffffu, hi != 0u);
}

// ---------------- Threefry-2x32 (JAX partitionable semantics) ----------------
__host__ __device__ constexpr unsigned rotl32(unsigned v, int s) {
    return (v << s) | (v >> (32 - s));
}
struct TFout { unsigned a, b; };
__host__ __device__ constexpr TFout tf2x32(unsigned k0, unsigned k1,
                                           unsigned x0, unsigned x1) {
    unsigned ks[3] = {k0, k1, k0 ^ k1 ^ 0x1BD11BDAu};
    const int R0[4] = {13, 15, 26, 6};
    const int R1[4] = {17, 29, 16, 24};
    x0 += ks[0]; x1 += ks[1];
    for (int i = 0; i < 5; i++) {
        for (int j = 0; j < 4; j++) {
            int r = (i % 2 == 0) ? R0[j] : R1[j];
            x0 += x1; x1 = rotl32(x1, r); x1 ^= x0;
        }
        x0 += ks[(i + 1) % 3];
        x1 += ks[(i + 2) % 3] + (unsigned)(i + 1);
    }
    return {x0, x1};
}
constexpr TFout KEY1 = tf2x32(0u, 42u, 0u, 0u);
constexpr TFout KEY2 = tf2x32(0u, 42u, 0u, 1u);

__device__ __forceinline__ float jax_uniform01(unsigned key0, unsigned key1,
                                               unsigned n) {
    TFout r = tf2x32(key0, key1, 0u, n);
    unsigned bits = r.a ^ r.b;
    return __uint_as_float(0x3F800000u | (bits >> 9)) - 1.0f;
}

// ---------------- edge index loader -------------------------------------------
__device__ __forceinline__ int ld_edge(const void* ei, long long pos, int is64) {
    return is64 ? (int)__ldg(((const long long*)ei) + pos)
                : __ldg(((const int*)ei) + pos);
}

// ---------------- K1: degree histogram over src + fused max ------------------
__global__ void __launch_bounds__(256)
k_degree(const void* __restrict__ ei, long long E) {
    int tid = threadIdx.x;
    int is64 = detect_is64(ei);
    long long e = (long long)blockIdx.x * 256 + tid;
    int cand = 0;
    if (e < E) {
        int s = ld_edge(ei, e, is64);
        cand = atomicAdd(&g_deg[s], 1) + 1;
    }
#pragma unroll
    for (int o = 16; o; o >>= 1)
        cand = max(cand, __shfl_xor_sync(0xffffffffu, cand, o));
    __shared__ int sm[8];
    if ((tid & 31) == 0) sm[tid >> 5] = cand;
    __syncthreads();
    if (tid < 8) {
        int t = sm[tid];
#pragma unroll
        for (int o = 4; o; o >>= 1) t = max(t, __shfl_xor_sync(0xffu, t, o));
        if (tid == 0) atomicMax(&g_degmax, t);
    }
}

// ---------------- K2: per-node precompute (2 threads per node) ----------------
__global__ void __launch_bounds__(NT)
k_nodeA(const float* __restrict__ x,
        const float* __restrict__ attn_w, const float* __restrict__ attn_b,
        const float* __restrict__ w_w,  const float* __restrict__ w_b,
        const float* __restrict__ t1w,  const float* __restrict__ t1b,
        int N, float Ef) {
    __shared__ float  s_x[BN * 33];      // 8.4 KB, conflict-free layout
    __shared__ float4 s_attn[AA * 32];   // [5][128]
    __shared__ float4 s_w[AA * 64];      // [5][256]
    __shared__ float4 s_t1wT[AA * 16];   // transposed [5][64]
    __shared__ float4 s_t1b4[16];
    __shared__ float  s_ab[AA], s_wb[AA];
    int tid = threadIdx.x;
    for (int i = tid; i < AA * 32; i += NT) s_attn[i] = ((const float4*)attn_w)[i];
    for (int i = tid; i < AA * 64; i += NT) s_w[i]    = ((const float4*)w_w)[i];
    for (int idx = tid; idx < AA * HH; idx += NT) {
        int i = idx / HH, j = idx % HH;                // t1w is [64][5]
        ((float*)s_t1wT)[i * HH + j] = t1w[j * AA + i];
    }
    for (int i = tid; i < 16; i += NT) s_t1b4[i] = ((const float4*)t1b)[i];
    if (tid < AA) { s_ab[tid] = attn_b[tid]; s_wb[tid] = w_b[tid]; }
    __syncthreads();

    int nbase = blockIdx.x * BN;
    int r = tid >> 1, h = tid & 1;
    int n = nbase + r;

    float pa[AA], ps[AA], pd[AA];
#pragma unroll
    for (int k = 0; k < AA; k++) { pa[k] = 0.f; ps[k] = 0.f; pd[k] = 0.f; }

    const float4* xg = (const float4*)x;
#pragma unroll
    for (int ch = 0; ch < 4; ch++) {
        if (ch) __syncthreads();
#pragma unroll
        for (int it = 0; it < 4; it++) {
            int idx = it * NT + tid;
            int rr = idx >> 3, c = idx & 7;
            int gn = nbase + rr;
            float4 v = make_float4(0.f, 0.f, 0.f, 0.f);
            if (gn < N) v = __ldg(xg + (size_t)gn * 32 + ch * 8 + c);
            float* p = s_x + rr * 33 + c * 4;
            p[0] = v.x; p[1] = v.y; p[2] = v.z; p[3] = v.w;
        }
        __syncthreads();
        const float* xr = s_x + r * 33 + h * 16;
#pragma unroll
        for (int j = 0; j < 4; j++) {
            float x0 = xr[j*4+0], x1 = xr[j*4+1];
            float x2 = xr[j*4+2], x3 = xr[j*4+3];
            int c = ch * 8 + h * 4 + j;   // halves 16 banks apart: dual-bcast
#pragma unroll
            for (int k = 0; k < AA; k++) {
                float4 av = s_attn[k * 32 + c];
                pa[k] += x0*av.x + x1*av.y + x2*av.z + x3*av.w;
                float4 sv = s_w[k * 64 + c];
                ps[k] += x0*sv.x + x1*sv.y + x2*sv.z + x3*sv.w;
                float4 dv = s_w[k * 64 + 32 + c];
                pd[k] += x0*dv.x + x1*dv.y + x2*dv.z + x3*dv.w;
            }
        }
    }
#pragma unroll
    for (int k = 0; k < AA; k++) {
        pa[k] += __shfl_xor_sync(0xffffffffu, pa[k], 1);
        ps[k] += __shfl_xor_sync(0xffffffffu, ps[k], 1);
        pd[k] += __shfl_xor_sync(0xffffffffu, pd[k], 1);
    }
#pragma unroll
    for (int k = 0; k < AA; k++) { pa[k] += s_ab[k]; ps[k] += s_wb[k]; }

    float m = pa[0];
#pragma unroll
    for (int k = 1; k < AA; k++) m = fmaxf(m, pa[k]);
    float ev[AA], sum = 0.f;
#pragma unroll
    for (int k = 0; k < AA; k++) { ev[k] = __expf(pa[k] - m); sum += ev[k]; }
    float inv = __fdividef(1.0f, sum);

    bool ok = (n < N);
    if (ok && h == 0) {
        *(float4*)(g_aw8 + (size_t)n * 8) =
            make_float4(ev[0]*inv, ev[1]*inv, ev[2]*inv, ev[3]*inv);
        g_aw8[(size_t)n * 8 + 4] = ev[4] * inv;
        *(float4*)(g_xs8 + (size_t)n * 8) = make_float4(ps[0], ps[1], ps[2], ps[3]);
        g_xs8[(size_t)n * 8 + 4] = ps[4];
    }
    if (ok && h == 1) {
        *(float4*)(g_xd8 + (size_t)n * 8) = make_float4(pd[0], pd[1], pd[2], pd[3]);
        g_xd8[(size_t)n * 8 + 4] = pd[4];
        // re-zero this node's B4 accumulator for the upcoming k_edge pass
        *(float4*)(g_B4 + (size_t)n * 4) = make_float4(0.f, 0.f, 0.f, 0.f);
    }

    // topology features + hidden layer
    int nc = (n < N) ? n : (N - 1);
    float deg   = (float)__ldg(&g_deg[nc]);
    float dmaxf = (float)g_degmax;
    float meanf = Ef / (float)N;
    unsigned kk0 = h ? KEY2.a : KEY1.a;
    unsigned kk1 = h ? KEY2.b : KEY1.b;
    float u_own   = jax_uniform01(kk0, kk1, (unsigned)n);
    float u_other = __shfl_xor_sync(0xffffffffu, u_own, 1);
    float u1 = h ? u_other : u_own;   // KEY1 stream
    float u2 = h ? u_own   : u_other; // KEY2 stream

    float tv[5];
    tv[0] = deg / (dmaxf + 1e-6f);
    tv[1] = u1 * 0.5f + 0.25f;
    tv[2] = deg / (Ef + 1e-6f);
    tv[3] = 1.0f / (1.0f + __expf(-(deg - meanf)));
    tv[4] = u2;

    if (ok) {
        float4* hout = (float4*)(g_h + (size_t)n * HH);
#pragma unroll
        for (int jc = 0; jc < 8; jc++) {
            int jc4 = h * 8 + jc;
            float4 hv = s_t1b4[jc4];
#pragma unroll
            for (int i = 0; i < AA; i++) {
                float4 wv = s_t1wT[i * 16 + jc4];
                hv.x += tv[i] * wv.x; hv.y += tv[i] * wv.y;
                hv.z += tv[i] * wv.z; hv.w += tv[i] * wv.w;
            }
            hv.x = fmaxf(hv.x, 0.f); hv.y = fmaxf(hv.y, 0.f);
            hv.z = fmaxf(hv.z, 0.f); hv.w = fmaxf(hv.w, 0.f);
            hout[jc4] = hv;
        }
    }
}

// ---------------- K3: edge kernel — thread-per-edge softmax, f32x2 store -----
__global__ void __launch_bounds__(256)
k_edge(const void* __restrict__ ei, long long E,
       const float* __restrict__ anchor, float* __restrict__ outE) {
    __shared__ unsigned long long s_bp[5][256];   // packed (b,b), column-major
    int tid  = threadIdx.x;
    int lane = tid & 31;
    int warp = tid >> 5;
    int is64 = detect_is64(ei);

    unsigned long long alo[AA], ahi[AA];
#pragma unroll
    for (int k = 0; k < AA; k++) {
        float4 a = __ldg(((const float4*)anchor) + k * 32 + lane);
        alo[k] = packf2(a.x, a.y);
        ahi[k] = packf2(a.z, a.w);
    }

    long long e = (long long)blockIdx.x * 256 + tid;
    if (e < E) {
        int src = ld_edge(ei, e, is64);
        int dst = ld_edge(ei, E + e, is64);
        float4 s4 = __ldg((const float4*)(g_xs8 + (size_t)src * 8));
        float  s5 = __ldg(g_xs8 + (size_t)src * 8 + 4);
        float4 d4 = __ldg((const float4*)(g_xd8 + (size_t)dst * 8));
        float  d5 = __ldg(g_xd8 + (size_t)dst * 8 + 4);
        float l[5];
        l[0] = s4.x + d4.x; l[1] = s4.y + d4.y; l[2] = s4.z + d4.z;
        l[3] = s4.w + d4.w; l[4] = s5 + d5;
#pragma unroll
        for (int k = 0; k < 5; k++) l[k] = fmaxf(l[k], 0.01f * l[k]); // leaky
        float m = l[0];
#pragma unroll
        for (int k = 1; k < 5; k++) m = fmaxf(m, l[k]);
        float ev[5], sum = 0.f;
#pragma unroll
        for (int k = 0; k < 5; k++) { ev[k] = __expf(l[k] - m); sum += ev[k]; }
        float inv = __fdividef(1.0f, sum);
        float b[5];
#pragma unroll
        for (int k = 0; k < 5; k++) b[k] = ev[k] * inv;
        red_add_v4(g_B4 + (size_t)src * 4, b[0], b[1], b[2], b[3]);
#pragma unroll
        for (int k = 0; k < 5; k++) s_bp[k][tid] = pack2(b[k]);  // conflict-free
    }
    __syncwarp();

    long long base = (long long)blockIdx.x * 256 + warp * 32;
    float4* o4 = (float4*)outE;
    int nfull = (base + 32 <= E) ? 32 : (int)(E > base ? E - base : 0);
    if (nfull == 32) {
#pragma unroll 4
        for (int j = 0; j < 32; j++) {
            int sb = warp * 32 + j;                    // uniform -> broadcast
            unsigned long long p0 = s_bp[0][sb], p1 = s_bp[1][sb],
                               p2 = s_bp[2][sb], p3 = s_bp[3][sb],
                               p4 = s_bp[4][sb];
            unsigned long long lo = mul2(p0, alo[0]);
            lo = fma2(p1, alo[1], lo); lo = fma2(p2, alo[2], lo);
            lo = fma2(p3, alo[3], lo); lo = fma2(p4, alo[4], lo);
            unsigned long long hi = mul2(p0, ahi[0]);
            hi = fma2(p1, ahi[1], hi); hi = fma2(p2, ahi[2], hi);
            hi = fma2(p3, ahi[3], hi); hi = fma2(p4, ahi[4], hi);
            float4 o;
            unpack2(lo, o.x, o.y);
            unpack2(hi, o.z, o.w);
            __stcs(o4 + (size_t)(base + j) * 32 + lane, o);
        }
    } else {
        for (int j = 0; j < nfull; j++) {
            int sb = warp * 32 + j;
            unsigned long long p0 = s_bp[0][sb], p1 = s_bp[1][sb],
                               p2 = s_bp[2][sb], p3 = s_bp[3][sb],
                               p4 = s_bp[4][sb];
            unsigned long long lo = mul2(p0, alo[0]);
            lo = fma2(p1, alo[1], lo); lo = fma2(p2, alo[2], lo);
            lo = fma2(p3, alo[3], lo); lo = fma2(p4, alo[4], lo);
            unsigned long long hi = mul2(p0, ahi[0]);
            hi = fma2(p1, ahi[1], hi); hi = fma2(p2, ahi[2], hi);
            hi = fma2(p3, ahi[3], hi); hi = fma2(p4, ahi[4], hi);
            float4 o;
            unpack2(lo, o.x, o.y);
            unpack2(hi, o.z, o.w);
            __stcs(o4 + (size_t)(base + j) * 32 + lane, o);
        }
    }
}

// ---------------- K4: final per-node (smem-staged h, j-split f32x2 GEMM) -----
// Tile = 32 nodes. Compute phase: warp (jh = w>>2) covers half the j-range for
// ALL 32 nodes with wp16 (32 regs), partials -> smem. Finalize phase: warp
// (half = w>>2) combines partials + epilogue for its 16 nodes. 3 blocks/SM.
__global__ void __launch_bounds__(256, 3)
k_final(const float* __restrict__ x,
        const float* __restrict__ node_anchor, const float* __restrict__ anchor,
        const float* __restrict__ t2w, const float* __restrict__ t2b,
        float* __restrict__ outF, int N) {
    __shared__ float4 s_h4[32 * 16];    // 32 nodes x 64 floats (8 KB)
    __shared__ float  s_accA[32 * DD];  // jh=0 partials (16 KB)
    __shared__ float  s_accB[32 * DD];  // jh=1 partials (16 KB)
    __shared__ float4 s_B[32];
    __shared__ float4 s_aw[32];
    __shared__ float  s_aw5[32];
    __shared__ float  s_degf[32];

    int tid  = threadIdx.x;
    int lane = tid & 31;
    int warp = tid >> 5;
    int jh   = warp >> 2;          // compute phase: j-half
    int cg   = warp & 3;
    int col  = cg * 32 + lane;

    // half of t2_w row for this column, packed: pairs p = jh*16 .. jh*16+15
    unsigned long long wp16[16];
#pragma unroll
    for (int j4 = 0; j4 < 8; j4++) {
        float4 wv = ((const float4*)t2w)[(size_t)col * 16 + jh * 8 + j4];
        wp16[2*j4+0] = packf2(wv.x, wv.y);
        wp16[2*j4+1] = packf2(wv.z, wv.w);
    }
    float areg[AA], nareg[AA];
#pragma unroll
    for (int k = 0; k < AA; k++) {
        areg[k]  = __ldg(&anchor[k * DD + col]);
        nareg[k] = __ldg(&node_anchor[k * DD + col]);
    }
    float bias = __ldg(&t2b[col]);
    float* s_out = jh ? s_accB : s_accA;

    int ntiles = (N + 31) >> 5;
    for (int tile = blockIdx.x; tile < ntiles; tile += gridDim.x) {
        int nb = tile << 5;
        __syncthreads();                 // protect smem reuse across tiles
        // ---- stage 32 h rows, coalesced ----
#pragma unroll
        for (int k = 0; k < 2; k++) {
            int idx = k * 256 + tid;
            int row = idx >> 4, c = idx & 15;
            int gn = nb + row;
            float4 v = make_float4(0.f, 0.f, 0.f, 0.f);
            if (gn < N) v = __ldg(((const float4*)g_h) + (size_t)gn * 16 + c);
            s_h4[idx] = v;
        }
        if (tid < 32) {
            int gn = nb + tid;
            if (gn < N) {
                s_B[tid]    = *(const float4*)(g_B4 + (size_t)gn * 4);
                s_aw[tid]   = *(const float4*)(g_aw8 + (size_t)gn * 8);
                s_aw5[tid]  = g_aw8[(size_t)gn * 8 + 4];
                s_degf[tid] = (float)g_deg[gn];
                g_deg[gn]   = 0;   // re-zero for next graph replay
            }
        }
        __syncthreads();
        // ---- compute phase: each warp does its j-half for all 32 nodes ----
#pragma unroll 2
        for (int nl = 0; nl < 32; nl++) {
            const ulonglong2* hrow =
                (const ulonglong2*)(s_h4 + nl * 16) + jh * 8;
            unsigned long long a0 = 0ULL, a1 = 0ULL, a2 = 0ULL, a3 = 0ULL;
#pragma unroll
            for (int q = 0; q < 2; q++) {               // broadcast LDS.128
                ulonglong2 hA = hrow[q*4+0], hB = hrow[q*4+1],
                           hC = hrow[q*4+2], hD = hrow[q*4+3];
                a0 = fma2(hA.x, wp16[8*q+0], a0);
                a1 = fma2(hA.y, wp16[8*q+1], a1);
                a2 = fma2(hB.x, wp16[8*q+2], a2);
                a3 = fma2(hB.y, wp16[8*q+3], a3);
                a0 = fma2(hC.x, wp16[8*q+4], a0);
                a1 = fma2(hC.y, wp16[8*q+5], a1);
                a2 = fma2(hD.x, wp16[8*q+6], a2);
                a3 = fma2(hD.y, wp16[8*q+7], a3);
            }
            a0 = fma2(a1, pack2(1.0f), a0);
            a2 = fma2(a3, pack2(1.0f), a2);
            float s0, s1, s2, s3;
            unpack2(a0, s0, s1);
            unpack2(a2, s2, s3);
            s_out[nl * DD + col] = (s0 + s1) + (s2 + s3);  // conflict-free STS
        }
        __syncthreads();
        // ---- finalize: warp (half = jh) handles its 16 nodes, same col ----
#pragma unroll 2
        for (int j = 0; j < 16; j++) {
            int nl = jh * 16 + j;
            int gn = nb + nl;
            if (gn >= N) break;
            float xv  = x[(size_t)gn * DD + col];         // coalesced
            float acc = bias + s_accA[nl * DD + col] + s_accB[nl * DD + col];

            float4 B   = s_B[nl];                         // broadcast LDS
            float deg  = s_degf[nl];
            float4 aw4 = s_aw[nl];
            float aw5  = s_aw5[nl];
            float B4v  = deg - B.x - B.y - B.z - B.w;
            float agg  = B.x*areg[0] + B.y*areg[1] + B.z*areg[2] + B.w*areg[3]
                       + B4v*areg[4];
            float np   = aw4.x*nareg[0] + aw4.y*nareg[1] + aw4.z*nareg[2]
                       + aw4.w*nareg[3] + aw5*nareg[4];
            outF[(size_t)gn * DD + col] = xv + np + acc * agg;
        }
    }
}

// ---------------- launch ------------------------------------------------------
extern "C" void kernel_launch(void* const* d_in, const int* in_sizes, int n_in,
                              void* d_out, int out_size) {
    const float* x           = (const float*)d_in[0];
    const void*  ei          = d_in[1];
    const float* anchor      = (const float*)d_in[3];
    const float* w_w         = (const float*)d_in[4];
    const float* w_b         = (const float*)d_in[5];
    const float* node_anchor = (const float*)d_in[6];
    const float* attn_w      = (const float*)d_in[7];
    const float* attn_b      = (const float*)d_in[8];
    const float* t1w         = (const float*)d_in[9];
    const float* t1b         = (const float*)d_in[10];
    const float* t2w         = (const float*)d_in[11];
    const float* t2b         = (const float*)d_in[12];

    int       N  = in_sizes[0] / DD;
    long long E  = (long long)in_sizes[1] / 2;
    float     Ef = (float)E;

    float* outF = (float*)d_out;                  // final_x [N, D]
    float* outE = outF + (size_t)N * DD;          // edge_prompt [E, D]

    k_degree<<<(unsigned)((E + 255) / 256), 256>>>(ei, E);
    k_nodeA <<<(N + BN - 1) / BN, NT>>>(x, attn_w, attn_b, w_w, w_b,
                                        t1w, t1b, N, Ef);
    k_edge  <<<(unsigned)((E + 255) / 256), 256>>>(ei, E, anchor, outE);
    k_final <<<592, 256>>>(x, node_anchor, anchor, t2w, t2b, outF, N);
}

// round 15
// speedup vs baseline: 1.5309x; 1.1295x over previous
#include <cuda_runtime.h>
#include <cstdint>
#include <cstddef>

// Problem constants (reference: N=50000, D=128, E=800000, A=5)
#define NMAX 50000
#define DD 128
#define AA 5
#define HH 64
#define BN 64    // nodes per block in k_nodeA
#define NT 128   // threads per block in k_nodeA (2 threads per node)

// ---------------- scratch (static device globals; zero-init at module load) --
// Invariant: g_deg and g_B4 are zero at entry of every kernel_launch call:
// load-time zero covers the first call; k_nodeA re-zeroes g_B4 (before k_edge
// accumulates) and k_final re-zeroes g_deg at tile-staging time (each node's
// deg is read only by its own tile's block).
__device__ __align__(16) float g_B4 [NMAX*4];  // edge softmax sums (4 comps)
__device__ __align__(16) float g_xs8[NMAX*8];  // x @ w[:, :128]^T + bias (pad)
__device__ __align__(16) float g_xd8[NMAX*8];  // x @ w[:, 128:]^T (pad)
__device__ __align__(16) float g_aw8[NMAX*8];  // attention softmax (pad)
__device__ __align__(16) float g_h  [NMAX*HH]; // relu(topo @ t1_w^T + t1_b)
__device__ int   g_deg[NMAX];
__device__ int   g_degmax;                     // monotone max; stable across replays

// ---------------- f32x2 packed math helpers ----------------------------------
__device__ __forceinline__ unsigned long long pack2(float v) {
    unsigned long long r;
    asm("mov.b64 %0, {%1, %1};" : "=l"(r) : "f"(v));
    return r;
}
__device__ __forceinline__ unsigned long long packf2(float x, float y) {
    unsigned long long r;
    asm("mov.b64 %0, {%1, %2};" : "=l"(r) : "f"(x), "f"(y));
    return r;
}
__device__ __forceinline__ unsigned long long mul2(unsigned long long a,
                                                   unsigned long long b) {
    unsigned long long d;
    asm("mul.rn.f32x2 %0, %1, %2;" : "=l"(d) : "l"(a), "l"(b));
    return d;
}
__device__ __forceinline__ unsigned long long fma2(unsigned long long a,
                                                   unsigned long long b,
                                                   unsigned long long c) {
    unsigned long long d;
    asm("fma.rn.f32x2 %0, %1, %2, %3;" : "=l"(d) : "l"(a), "l"(b), "l"(c));
    return d;
}
__device__ __forceinline__ void unpack2(unsigned long long v, float& x, float& y) {
    asm("mov.b64 {%0, %1}, %2;" : "=f"(x), "=f"(y) : "l"(v));
}
// vectorized float4 reduction (PTX ISA 8.1+, sm_90+)
__device__ __forceinline__ void red_add_v4(float* p, float b0, float b1,
                                           float b2, float b3) {
    asm volatile(
        "{\n\t.reg .u64 pg;\n\t"
        "cvta.to.global.u64 pg, %0;\n\t"
        "red.global.add.v4.f32 [pg], {%1, %2, %3, %4};\n\t}"
        :: "l"(p), "f"(b0), "f"(b1), "f"(b2), "f"(b3) : "memory");
}

// ---------------- per-warp int64/int32 edge-index detection ------------------
__device__ __forceinline__ int detect_is64(const void* ei) {
    unsigned hi = ((const unsigned*)ei)[2 * (threadIdx.x & 31) + 1];
    return !__any_sync(0xffffffffu, hi != 0u);
}

// ---------------- Threefry-2x32 (JAX partitionable semantics) ----------------
__host__ __device__ constexpr unsigned rotl32(unsigned v, int s) {
    return (v << s) | (v >> (32 - s));
}
struct TFout { unsigned a, b; };
__host__ __device__ constexpr TFout tf2x32(unsigned k0, unsigned k1,
                                           unsigned x0, unsigned x1) {
    unsigned ks[3] = {k0, k1, k0 ^ k1 ^ 0x1BD11BDAu};
    const int R0[4] = {13, 15, 26, 6};
    const int R1[4] = {17, 29, 16, 24};
    x0 += ks[0]; x1 += ks[1];
    for (int i = 0; i < 5; i++) {
        for (int j = 0; j < 4; j++) {
            int r = (i % 2 == 0) ? R0[j] : R1[j];
            x0 += x1; x1 = rotl32(x1, r); x1 ^= x0;
        }
        x0 += ks[(i + 1) % 3];
        x1 += ks[(i + 2) % 3] + (unsigned)(i + 1);
    }
    return {x0, x1};
}
constexpr TFout KEY1 = tf2x32(0u, 42u, 0u, 0u);
constexpr TFout KEY2 = tf2x32(0u, 42u, 0u, 1u);

__device__ __forceinline__ float jax_uniform01(unsigned key0, unsigned key1,
                                               unsigned n) {
    TFout r = tf2x32(key0, key1, 0u, n);
    unsigned bits = r.a ^ r.b;
    return __uint_as_float(0x3F800000u | (bits >> 9)) - 1.0f;
}

// ---------------- edge index loader -------------------------------------------
__device__ __forceinline__ int ld_edge(const void* ei, long long pos, int is64) {
    return is64 ? (int)__ldg(((const long long*)ei) + pos)
                : __ldg(((const int*)ei) + pos);
}

// ---------------- K1: degree histogram over src + fused max ------------------
__global__ void __launch_bounds__(256)
k_degree(const void* __restrict__ ei, long long E) {
    int tid = threadIdx.x;
    int is64 = detect_is64(ei);
    long long e = (long long)blockIdx.x * 256 + tid;
    int cand = 0;
    if (e < E) {
        int s = ld_edge(ei, e, is64);
        cand = atomicAdd(&g_deg[s], 1) + 1;
    }
#pragma unroll
    for (int o = 16; o; o >>= 1)
        cand = max(cand, __shfl_xor_sync(0xffffffffu, cand, o));
    __shared__ int sm[8];
    if ((tid & 31) == 0) sm[tid >> 5] = cand;
    __syncthreads();
    if (tid < 8) {
        int t = sm[tid];
#pragma unroll
        for (int o = 4; o; o >>= 1) t = max(t, __shfl_xor_sync(0xffu, t, o));
        if (tid == 0) atomicMax(&g_degmax, t);
    }
}

// ---------------- K2: per-node precompute (2 threads per node) ----------------
__global__ void __launch_bounds__(NT)
k_nodeA(const float* __restrict__ x,
        const float* __restrict__ attn_w, const float* __restrict__ attn_b,
        const float* __restrict__ w_w,  const float* __restrict__ w_b,
        const float* __restrict__ t1w,  const float* __restrict__ t1b,
        int N, float Ef) {
    __shared__ float  s_x[BN * 33];      // 8.4 KB, conflict-free layout
    __shared__ float4 s_attn[AA * 32];   // [5][128]
    __shared__ float4 s_w[AA * 64];      // [5][256]
    __shared__ float4 s_t1wT[AA * 16];   // transposed [5][64]
    __shared__ float4 s_t1b4[16];
    __shared__ float  s_ab[AA], s_wb[AA];
    int tid = threadIdx.x;
    for (int i = tid; i < AA * 32; i += NT) s_attn[i] = ((const float4*)attn_w)[i];
    for (int i = tid; i < AA * 64; i += NT) s_w[i]    = ((const float4*)w_w)[i];
    for (int idx = tid; idx < AA * HH; idx += NT) {
        int i = idx / HH, j = idx % HH;                // t1w is [64][5]
        ((float*)s_t1wT)[i * HH + j] = t1w[j * AA + i];
    }
    for (int i = tid; i < 16; i += NT) s_t1b4[i] = ((const float4*)t1b)[i];
    if (tid < AA) { s_ab[tid] = attn_b[tid]; s_wb[tid] = w_b[tid]; }
    __syncthreads();

    int nbase = blockIdx.x * BN;
    int r = tid >> 1, h = tid & 1;
    int n = nbase + r;

    float pa[AA], ps[AA], pd[AA];
#pragma unroll
    for (int k = 0; k < AA; k++) { pa[k] = 0.f; ps[k] = 0.f; pd[k] = 0.f; }

    const float4* xg = (const float4*)x;
#pragma unroll
    for (int ch = 0; ch < 4; ch++) {
        if (ch) __syncthreads();
#pragma unroll
        for (int it = 0; it < 4; it++) {
            int idx = it * NT + tid;
            int rr = idx >> 3, c = idx & 7;
            int gn = nbase + rr;
            float4 v = make_float4(0.f, 0.f, 0.f, 0.f);
            if (gn < N) v = __ldg(xg + (size_t)gn * 32 + ch * 8 + c);
            float* p = s_x + rr * 33 + c * 4;
            p[0] = v.x; p[1] = v.y; p[2] = v.z; p[3] = v.w;
        }
        __syncthreads();
        const float* xr = s_x + r * 33 + h * 16;
#pragma unroll
        for (int j = 0; j < 4; j++) {
            float x0 = xr[j*4+0], x1 = xr[j*4+1];
            float x2 = xr[j*4+2], x3 = xr[j*4+3];
            int c = ch * 8 + h * 4 + j;   // halves 16 banks apart: dual-bcast
#pragma unroll
            for (int k = 0; k < AA; k++) {
                float4 av = s_attn[k * 32 + c];
                pa[k] += x0*av.x + x1*av.y + x2*av.z + x3*av.w;
                float4 sv = s_w[k * 64 + c];
                ps[k] += x0*sv.x + x1*sv.y + x2*sv.z + x3*sv.w;
                float4 dv = s_w[k * 64 + 32 + c];
                pd[k] += x0*dv.x + x1*dv.y + x2*dv.z + x3*dv.w;
            }
        }
    }
#pragma unroll
    for (int k = 0; k < AA; k++) {
        pa[k] += __shfl_xor_sync(0xffffffffu, pa[k], 1);
        ps[k] += __shfl_xor_sync(0xffffffffu, ps[k], 1);
        pd[k] += __shfl_xor_sync(0xffffffffu, pd[k], 1);
    }
#pragma unroll
    for (int k = 0; k < AA; k++) { pa[k] += s_ab[k]; ps[k] += s_wb[k]; }

    float m = pa[0];
#pragma unroll
    for (int k = 1; k < AA; k++) m = fmaxf(m, pa[k]);
    float ev[AA], sum = 0.f;
#pragma unroll
    for (int k = 0; k < AA; k++) { ev[k] = __expf(pa[k] - m); sum += ev[k]; }
    float inv = __fdividef(1.0f, sum);

    bool ok = (n < N);
    if (ok && h == 0) {
        *(float4*)(g_aw8 + (size_t)n * 8) =
            make_float4(ev[0]*inv, ev[1]*inv, ev[2]*inv, ev[3]*inv);
        g_aw8[(size_t)n * 8 + 4] = ev[4] * inv;
        *(float4*)(g_xs8 + (size_t)n * 8) = make_float4(ps[0], ps[1], ps[2], ps[3]);
        g_xs8[(size_t)n * 8 + 4] = ps[4];
    }
    if (ok && h == 1) {
        *(float4*)(g_xd8 + (size_t)n * 8) = make_float4(pd[0], pd[1], pd[2], pd[3]);
        g_xd8[(size_t)n * 8 + 4] = pd[4];
        // re-zero this node's B4 accumulator for the upcoming k_edge pass
        *(float4*)(g_B4 + (size_t)n * 4) = make_float4(0.f, 0.f, 0.f, 0.f);
    }

    // topology features + hidden layer
    int nc = (n < N) ? n : (N - 1);
    float deg   = (float)__ldg(&g_deg[nc]);
    float dmaxf = (float)g_degmax;
    float meanf = Ef / (float)N;
    unsigned kk0 = h ? KEY2.a : KEY1.a;
    unsigned kk1 = h ? KEY2.b : KEY1.b;
    float u_own   = jax_uniform01(kk0, kk1, (unsigned)n);
    float u_other = __shfl_xor_sync(0xffffffffu, u_own, 1);
    float u1 = h ? u_other : u_own;   // KEY1 stream
    float u2 = h ? u_own   : u_other; // KEY2 stream

    float tv[5];
    tv[0] = deg / (dmaxf + 1e-6f);
    tv[1] = u1 * 0.5f + 0.25f;
    tv[2] = deg / (Ef + 1e-6f);
    tv[3] = 1.0f / (1.0f + __expf(-(deg - meanf)));
    tv[4] = u2;

    if (ok) {
        float4* hout = (float4*)(g_h + (size_t)n * HH);
#pragma unroll
        for (int jc = 0; jc < 8; jc++) {
            int jc4 = h * 8 + jc;
            float4 hv = s_t1b4[jc4];
#pragma unroll
            for (int i = 0; i < AA; i++) {
                float4 wv = s_t1wT[i * 16 + jc4];
                hv.x += tv[i] * wv.x; hv.y += tv[i] * wv.y;
                hv.z += tv[i] * wv.z; hv.w += tv[i] * wv.w;
            }
            hv.x = fmaxf(hv.x, 0.f); hv.y = fmaxf(hv.y, 0.f);
            hv.z = fmaxf(hv.z, 0.f); hv.w = fmaxf(hv.w, 0.f);
            hout[jc4] = hv;
        }
    }
}

// ---------------- K3: edge kernel — thread-per-edge softmax, f32x2 store -----
__global__ void __launch_bounds__(256)
k_edge(const void* __restrict__ ei, long long E,
       const float* __restrict__ anchor, float* __restrict__ outE) {
    __shared__ unsigned long long s_bp[5][256];   // packed (b,b), column-major
    int tid  = threadIdx.x;
    int lane = tid & 31;
    int warp = tid >> 5;
    int is64 = detect_is64(ei);

    unsigned long long alo[AA], ahi[AA];
#pragma unroll
    for (int k = 0; k < AA; k++) {
        float4 a = __ldg(((const float4*)anchor) + k * 32 + lane);
        alo[k] = packf2(a.x, a.y);
        ahi[k] = packf2(a.z, a.w);
    }

    long long e = (long long)blockIdx.x * 256 + tid;
    if (e < E) {
        int src = ld_edge(ei, e, is64);
        int dst = ld_edge(ei, E + e, is64);
        float4 s4 = __ldg((const float4*)(g_xs8 + (size_t)src * 8));
        float  s5 = __ldg(g_xs8 + (size_t)src * 8 + 4);
        float4 d4 = __ldg((const float4*)(g_xd8 + (size_t)dst * 8));
        float  d5 = __ldg(g_xd8 + (size_t)dst * 8 + 4);
        float l[5];
        l[0] = s4.x + d4.x; l[1] = s4.y + d4.y; l[2] = s4.z + d4.z;
        l[3] = s4.w + d4.w; l[4] = s5 + d5;
#pragma unroll
        for (int k = 0; k < 5; k++) l[k] = fmaxf(l[k], 0.01f * l[k]); // leaky
        float m = l[0];
#pragma unroll
        for (int k = 1; k < 5; k++) m = fmaxf(m, l[k]);
        float ev[5], sum = 0.f;
#pragma unroll
        for (int k = 0; k < 5; k++) { ev[k] = __expf(l[k] - m); sum += ev[k]; }
        float inv = __fdividef(1.0f, sum);
        float b[5];
#pragma unroll
        for (int k = 0; k < 5; k++) b[k] = ev[k] * inv;
        red_add_v4(g_B4 + (size_t)src * 4, b[0], b[1], b[2], b[3]);
#pragma unroll
        for (int k = 0; k < 5; k++) s_bp[k][tid] = pack2(b[k]);  // conflict-free
    }
    __syncwarp();

    long long base = (long long)blockIdx.x * 256 + warp * 32;
    float4* o4 = (float4*)outE;
    int nfull = (base + 32 <= E) ? 32 : (int)(E > base ? E - base : 0);
    if (nfull == 32) {
#pragma unroll 4
        for (int j = 0; j < 32; j++) {
            int sb = warp * 32 + j;                    // uniform -> broadcast
            unsigned long long p0 = s_bp[0][sb], p1 = s_bp[1][sb],
                               p2 = s_bp[2][sb], p3 = s_bp[3][sb],
                               p4 = s_bp[4][sb];
            unsigned long long lo = mul2(p0, alo[0]);
            lo = fma2(p1, alo[1], lo); lo = fma2(p2, alo[2], lo);
            lo = fma2(p3, alo[3], lo); lo = fma2(p4, alo[4], lo);
            unsigned long long hi = mul2(p0, ahi[0]);
            hi = fma2(p1, ahi[1], hi); hi = fma2(p2, ahi[2], hi);
            hi = fma2(p3, ahi[3], hi); hi = fma2(p4, ahi[4], hi);
            float4 o;
            unpack2(lo, o.x, o.y);
            unpack2(hi, o.z, o.w);
            __stcs(o4 + (size_t)(base + j) * 32 + lane, o);
        }
    } else {
        for (int j = 0; j < nfull; j++) {
            int sb = warp * 32 + j;
            unsigned long long p0 = s_bp[0][sb], p1 = s_bp[1][sb],
                               p2 = s_bp[2][sb], p3 = s_bp[3][sb],
                               p4 = s_bp[4][sb];
            unsigned long long lo = mul2(p0, alo[0]);
            lo = fma2(p1, alo[1], lo); lo = fma2(p2, alo[2], lo);
            lo = fma2(p3, alo[3], lo); lo = fma2(p4, alo[4], lo);
            unsigned long long hi = mul2(p0, ahi[0]);
            hi = fma2(p1, ahi[1], hi); hi = fma2(p2, ahi[2], hi);
            hi = fma2(p3, ahi[3], hi); hi = fma2(p4, ahi[4], hi);
            float4 o;
            unpack2(lo, o.x, o.y);
            unpack2(hi, o.z, o.w);
            __stcs(o4 + (size_t)(base + j) * 32 + lane, o);
        }
    }
}

// ---------------- K4: final per-node (smem-staged h+x, j-split f32x2 GEMM) ---
// Tile = 32 nodes. x tile also staged (deep-MLP batched with h) so finalize is
// all-smem. Compute phase unroll 4 for LDS->fma2 ILP.
__global__ void __launch_bounds__(256, 3)
k_final(const float* __restrict__ x,
        const float* __restrict__ node_anchor, const float* __restrict__ anchor,
        const float* __restrict__ t2w, const float* __restrict__ t2b,
        float* __restrict__ outF, int N) {
    __shared__ float4 s_h4[32 * 16];    // 32 nodes x 64 floats (8 KB)
    __shared__ float  s_xt[32 * DD];    // 32 nodes x 128 floats (16 KB)
    __shared__ float  s_accA[32 * DD];  // jh=0 partials (16 KB)
    __shared__ float  s_accB[32 * DD];  // jh=1 partials (16 KB)
    __shared__ float4 s_B[32];
    __shared__ float4 s_aw[32];
    __shared__ float  s_aw5[32];
    __shared__ float  s_degf[32];

    int tid  = threadIdx.x;
    int lane = tid & 31;
    int warp = tid >> 5;
    int jh   = warp >> 2;          // compute phase: j-half
    int cg   = warp & 3;
    int col  = cg * 32 + lane;

    // half of t2_w row for this column, packed: pairs p = jh*16 .. jh*16+15
    unsigned long long wp16[16];
#pragma unroll
    for (int j4 = 0; j4 < 8; j4++) {
        float4 wv = ((const float4*)t2w)[(size_t)col * 16 + jh * 8 + j4];
        wp16[2*j4+0] = packf2(wv.x, wv.y);
        wp16[2*j4+1] = packf2(wv.z, wv.w);
    }
    float areg[AA], nareg[AA];
#pragma unroll
    for (int k = 0; k < AA; k++) {
        areg[k]  = __ldg(&anchor[k * DD + col]);
        nareg[k] = __ldg(&node_anchor[k * DD + col]);
    }
    float bias = __ldg(&t2b[col]);
    float* s_out = jh ? s_accB : s_accA;

    int ntiles = (N + 31) >> 5;
    for (int tile = blockIdx.x; tile < ntiles; tile += gridDim.x) {
        int nb = tile << 5;
        __syncthreads();                 // protect smem reuse across tiles
        // ---- stage 32 h rows + 32 x rows, coalesced, deep MLP ----
#pragma unroll
        for (int k = 0; k < 2; k++) {
            int idx = k * 256 + tid;
            int row = idx >> 4, c = idx & 15;
            int gn = nb + row;
            float4 v = make_float4(0.f, 0.f, 0.f, 0.f);
            if (gn < N) v = __ldg(((const float4*)g_h) + (size_t)gn * 16 + c);
            s_h4[idx] = v;
        }
#pragma unroll
        for (int k = 0; k < 4; k++) {
            int idx = k * 256 + tid;
            int row = idx >> 5, c = idx & 31;
            int gn = nb + row;
            float4 v = make_float4(0.f, 0.f, 0.f, 0.f);
            if (gn < N) v = __ldg(((const float4*)x) + (size_t)gn * 32 + c);
            *(float4*)(s_xt + row * DD + c * 4) = v;
        }
        if (tid < 32) {
            int gn = nb + tid;
            if (gn < N) {
                s_B[tid]    = *(const float4*)(g_B4 + (size_t)gn * 4);
                s_aw[tid]   = *(const float4*)(g_aw8 + (size_t)gn * 8);
                s_aw5[tid]  = g_aw8[(size_t)gn * 8 + 4];
                s_degf[tid] = (float)g_deg[gn];
                g_deg[gn]   = 0;   // re-zero for next graph replay
            }
        }
        __syncthreads();
        // ---- compute phase: each warp does its j-half for all 32 nodes ----
#pragma unroll 4
        for (int nl = 0; nl < 32; nl++) {
            const ulonglong2* hrow =
                (const ulonglong2*)(s_h4 + nl * 16) + jh * 8;
            unsigned long long a0 = 0ULL, a1 = 0ULL, a2 = 0ULL, a3 = 0ULL;
#pragma unroll
            for (int q = 0; q < 2; q++) {               // broadcast LDS.128
                ulonglong2 hA = hrow[q*4+0], hB = hrow[q*4+1],
                           hC = hrow[q*4+2], hD = hrow[q*4+3];
                a0 = fma2(hA.x, wp16[8*q+0], a0);
                a1 = fma2(hA.y, wp16[8*q+1], a1);
                a2 = fma2(hB.x, wp16[8*q+2], a2);
                a3 = fma2(hB.y, wp16[8*q+3], a3);
                a0 = fma2(hC.x, wp16[8*q+4], a0);
                a1 = fma2(hC.y, wp16[8*q+5], a1);
                a2 = fma2(hD.x, wp16[8*q+6], a2);
                a3 = fma2(hD.y, wp16[8*q+7], a3);
            }
            a0 = fma2(a1, pack2(1.0f), a0);
            a2 = fma2(a3, pack2(1.0f), a2);
            float s0, s1, s2, s3;
            unpack2(a0, s0, s1);
            unpack2(a2, s2, s3);
            s_out[nl * DD + col] = (s0 + s1) + (s2 + s3);  // conflict-free STS
        }
        __syncthreads();
        // ---- finalize: warp (half = jh) handles its 16 nodes, all-smem ----
#pragma unroll 4
        for (int j = 0; j < 16; j++) {
            int nl = jh * 16 + j;
            int gn = nb + nl;
            if (gn >= N) break;
            float xv  = s_xt[nl * DD + col];              // conflict-free LDS
            float acc = bias + s_accA[nl * DD + col] + s_accB[nl * DD + col];

            float4 B   = s_B[nl];                         // broadcast LDS
            float deg  = s_degf[nl];
            float4 aw4 = s_aw[nl];
            float aw5  = s_aw5[nl];
            float B4v  = deg - B.x - B.y - B.z - B.w;
            float agg  = B.x*areg[0] + B.y*areg[1] + B.z*areg[2] + B.w*areg[3]
                       + B4v*areg[4];
            float np   = aw4.x*nareg[0] + aw4.y*nareg[1] + aw4.z*nareg[2]
                       + aw4.w*nareg[3] + aw5*nareg[4];
            outF[(size_t)gn * DD + col] = xv + np + acc * agg;
        }
    }
}

// ---------------- launch ------------------------------------------------------
extern "C" void kernel_launch(void* const* d_in, const int* in_sizes, int n_in,
                              void* d_out, int out_size) {
    const float* x           = (const float*)d_in[0];
    const void*  ei          = d_in[1];
    const float* anchor      = (const float*)d_in[3];
    const float* w_w         = (const float*)d_in[4];
    const float* w_b         = (const float*)d_in[5];
    const float* node_anchor = (const float*)d_in[6];
    const float* attn_w      = (const float*)d_in[7];
    const float* attn_b      = (const float*)d_in[8];
    const float* t1w         = (const float*)d_in[9];
    const float* t1b         = (const float*)d_in[10];
    const float* t2w         = (const float*)d_in[11];
    const float* t2b         = (const float*)d_in[12];

    int       N  = in_sizes[0] / DD;
    long long E  = (long long)in_sizes[1] / 2;
    float     Ef = (float)E;

    float* outF = (float*)d_out;                  // final_x [N, D]
    float* outE = outF + (size_t)N * DD;          // edge_prompt [E, D]

    k_degree<<<(unsigned)((E + 255) / 256), 256>>>(ei, E);
    k_nodeA <<<(N + BN - 1) / BN, NT>>>(x, attn_w, attn_b, w_w, w_b,
                                        t1w, t1b, N, Ef);
    k_edge  <<<(unsigned)((E + 255) / 256), 256>>>(ei, E, anchor, outE);
    k_final <<<592, 256>>>(x, node_anchor, anchor, t2w, t2b, outF, N);
}

// round 16
// speedup vs baseline: 1.6217x; 1.0593x over previous
#include <cuda_runtime.h>
#include <cstdint>
#include <cstddef>

// Problem constants (reference: N=50000, D=128, E=800000, A=5)
#define NMAX 50000
#define DD 128
#define AA 5
#define HH 64
#define BN 64    // nodes per block in k_nodeA
#define NT 128   // threads per block in k_nodeA (2 threads per node)

// ---------------- scratch (static device globals; zero-init at module load) --
// Invariant: g_deg and g_B4 are zero at entry of every kernel_launch call:
// load-time zero covers the first call; k_nodeA re-zeroes g_B4 (before k_edge
// accumulates) and k_final re-zeroes g_deg at tile-staging time.
__device__ __align__(16) float g_B4 [NMAX*4];  // edge softmax sums (4 comps)
__device__ __align__(16) float g_xs8[NMAX*8];  // x @ w[:, :128]^T + bias (pad)
__device__ __align__(16) float g_xd8[NMAX*8];  // x @ w[:, 128:]^T (pad)
__device__ __align__(16) float g_aw8[NMAX*8];  // attention softmax (pad)
__device__ __align__(16) float g_h  [NMAX*HH]; // relu(topo @ t1_w^T + t1_b)
__device__ int   g_deg[NMAX];
__device__ int   g_degmax;                     // monotone max; stable across replays

// ---------------- f32x2 packed math helpers ----------------------------------
__device__ __forceinline__ unsigned long long pack2(float v) {
    unsigned long long r;
    asm("mov.b64 %0, {%1, %1};" : "=l"(r) : "f"(v));
    return r;
}
__device__ __forceinline__ unsigned long long packf2(float x, float y) {
    unsigned long long r;
    asm("mov.b64 %0, {%1, %2};" : "=l"(r) : "f"(x), "f"(y));
    return r;
}
__device__ __forceinline__ unsigned long long mul2(unsigned long long a,
                                                   unsigned long long b) {
    unsigned long long d;
    asm("mul.rn.f32x2 %0, %1, %2;" : "=l"(d) : "l"(a), "l"(b));
    return d;
}
__device__ __forceinline__ unsigned long long fma2(unsigned long long a,
                                                   unsigned long long b,
                                                   unsigned long long c) {
    unsigned long long d;
    asm("fma.rn.f32x2 %0, %1, %2, %3;" : "=l"(d) : "l"(a), "l"(b), "l"(c));
    return d;
}
__device__ __forceinline__ void unpack2(unsigned long long v, float& x, float& y) {
    asm("mov.b64 {%0, %1}, %2;" : "=f"(x), "=f"(y) : "l"(v));
}
// vectorized float4 reduction (PTX ISA 8.1+, sm_90+)
__device__ __forceinline__ void red_add_v4(float* p, float b0, float b1,
                                           float b2, float b3) {
    asm volatile(
        "{\n\t.reg .u64 pg;\n\t"
        "cvta.to.global.u64 pg, %0;\n\t"
        "red.global.add.v4.f32 [pg], {%1, %2, %3, %4};\n\t}"
        :: "l"(p), "f"(b0), "f"(b1), "f"(b2), "f"(b3) : "memory");
}

// ---------------- per-warp int64/int32 edge-index detection ------------------
__device__ __forceinline__ int detect_is64(const void* ei) {
    unsigned hi = ((const unsigned*)ei)[2 * (threadIdx.x & 31) + 1];
    return !__any_sync(0xffffffffu, hi != 0u);
}

// ---------------- Threefry-2x32 (JAX partitionable semantics) ----------------
__host__ __device__ constexpr unsigned rotl32(unsigned v, int s) {
    return (v << s) | (v >> (32 - s));
}
struct TFout { unsigned a, b; };
__host__ __device__ constexpr TFout tf2x32(unsigned k0, unsigned k1,
                                           unsigned x0, unsigned x1) {
    unsigned ks[3] = {k0, k1, k0 ^ k1 ^ 0x1BD11BDAu};
    const int R0[4] = {13, 15, 26, 6};
    const int R1[4] = {17, 29, 16, 24};
    x0 += ks[0]; x1 += ks[1];
    for (int i = 0; i < 5; i++) {
        for (int j = 0; j < 4; j++) {
            int r = (i % 2 == 0) ? R0[j] : R1[j];
            x0 += x1; x1 = rotl32(x1, r); x1 ^= x0;
        }
        x0 += ks[(i + 1) % 3];
        x1 += ks[(i + 2) % 3] + (unsigned)(i + 1);
    }
    return {x0, x1};
}
constexpr TFout KEY1 = tf2x32(0u, 42u, 0u, 0u);
constexpr TFout KEY2 = tf2x32(0u, 42u, 0u, 1u);

__device__ __forceinline__ float jax_uniform01(unsigned key0, unsigned key1,
                                               unsigned n) {
    TFout r = tf2x32(key0, key1, 0u, n);
    unsigned bits = r.a ^ r.b;
    return __uint_as_float(0x3F800000u | (bits >> 9)) - 1.0f;
}

// ---------------- edge index loader -------------------------------------------
__device__ __forceinline__ int ld_edge(const void* ei, long long pos, int is64) {
    return is64 ? (int)__ldg(((const long long*)ei) + pos)
                : __ldg(((const int*)ei) + pos);
}

// ---------------- K1: degree histogram over src + fused max ------------------
__global__ void __launch_bounds__(256)
k_degree(const void* __restrict__ ei, long long E) {
    int tid = threadIdx.x;
    int is64 = detect_is64(ei);
    long long e = (long long)blockIdx.x * 256 + tid;
    int cand = 0;
    if (e < E) {
        int s = ld_edge(ei, e, is64);
        cand = atomicAdd(&g_deg[s], 1) + 1;
    }
#pragma unroll
    for (int o = 16; o; o >>= 1)
        cand = max(cand, __shfl_xor_sync(0xffffffffu, cand, o));
    __shared__ int sm[8];
    if ((tid & 31) == 0) sm[tid >> 5] = cand;
    __syncthreads();
    if (tid < 8) {
        int t = sm[tid];
#pragma unroll
        for (int o = 4; o; o >>= 1) t = max(t, __shfl_xor_sync(0xffu, t, o));
        if (tid == 0) atomicMax(&g_degmax, t);
    }
}

// ---------------- K2: per-node precompute (2 threads per node) ----------------
__global__ void __launch_bounds__(NT)
k_nodeA(const float* __restrict__ x,
        const float* __restrict__ attn_w, const float* __restrict__ attn_b,
        const float* __restrict__ w_w,  const float* __restrict__ w_b,
        const float* __restrict__ t1w,  const float* __restrict__ t1b,
        int N, float Ef) {
    __shared__ float  s_x[BN * 33];      // 8.4 KB, conflict-free layout
    __shared__ float4 s_attn[AA * 32];   // [5][128]
    __shared__ float4 s_w[AA * 64];      // [5][256]
    __shared__ float4 s_t1wT[AA * 16];   // transposed [5][64]
    __shared__ float4 s_t1b4[16];
    __shared__ float  s_ab[AA], s_wb[AA];
    int tid = threadIdx.x;
    for (int i = tid; i < AA * 32; i += NT) s_attn[i] = ((const float4*)attn_w)[i];
    for (int i = tid; i < AA * 64; i += NT) s_w[i]    = ((const float4*)w_w)[i];
    for (int idx = tid; idx < AA * HH; idx += NT) {
        int i = idx / HH, j = idx % HH;                // t1w is [64][5]
        ((float*)s_t1wT)[i * HH + j] = t1w[j * AA + i];
    }
    for (int i = tid; i < 16; i += NT) s_t1b4[i] = ((const float4*)t1b)[i];
    if (tid < AA) { s_ab[tid] = attn_b[tid]; s_wb[tid] = w_b[tid]; }
    __syncthreads();

    int nbase = blockIdx.x * BN;
    int r = tid >> 1, h = tid & 1;
    int n = nbase + r;

    float pa[AA], ps[AA], pd[AA];
#pragma unroll
    for (int k = 0; k < AA; k++) { pa[k] = 0.f; ps[k] = 0.f; pd[k] = 0.f; }

    const float4* xg = (const float4*)x;
#pragma unroll
    for (int ch = 0; ch < 4; ch++) {
        if (ch) __syncthreads();
#pragma unroll
        for (int it = 0; it < 4; it++) {
            int idx = it * NT + tid;
            int rr = idx >> 3, c = idx & 7;
            int gn = nbase + rr;
            float4 v = make_float4(0.f, 0.f, 0.f, 0.f);
            if (gn < N) v = __ldg(xg + (size_t)gn * 32 + ch * 8 + c);
            float* p = s_x + rr * 33 + c * 4;
            p[0] = v.x; p[1] = v.y; p[2] = v.z; p[3] = v.w;
        }
        __syncthreads();
        const float* xr = s_x + r * 33 + h * 16;
#pragma unroll
        for (int j = 0; j < 4; j++) {
            float x0 = xr[j*4+0], x1 = xr[j*4+1];
            float x2 = xr[j*4+2], x3 = xr[j*4+3];
            int c = ch * 8 + h * 4 + j;   // halves 16 banks apart: dual-bcast
#pragma unroll
            for (int k = 0; k < AA; k++) {
                float4 av = s_attn[k * 32 + c];
                pa[k] += x0*av.x + x1*av.y + x2*av.z + x3*av.w;
                float4 sv = s_w[k * 64 + c];
                ps[k] += x0*sv.x + x1*sv.y + x2*sv.z + x3*sv.w;
                float4 dv = s_w[k * 64 + 32 + c];
                pd[k] += x0*dv.x + x1*dv.y + x2*dv.z + x3*dv.w;
            }
        }
    }
#pragma unroll
    for (int k = 0; k < AA; k++) {
        pa[k] += __shfl_xor_sync(0xffffffffu, pa[k], 1);
        ps[k] += __shfl_xor_sync(0xffffffffu, ps[k], 1);
        pd[k] += __shfl_xor_sync(0xffffffffu, pd[k], 1);
    }
#pragma unroll
    for (int k = 0; k < AA; k++) { pa[k] += s_ab[k]; ps[k] += s_wb[k]; }

    float m = pa[0];
#pragma unroll
    for (int k = 1; k < AA; k++) m = fmaxf(m, pa[k]);
    float ev[AA], sum = 0.f;
#pragma unroll
    for (int k = 0; k < AA; k++) { ev[k] = __expf(pa[k] - m); sum += ev[k]; }
    float inv = __fdividef(1.0f, sum);

    bool ok = (n < N);
    if (ok && h == 0) {
        *(float4*)(g_aw8 + (size_t)n * 8) =
            make_float4(ev[0]*inv, ev[1]*inv, ev[2]*inv, ev[3]*inv);
        g_aw8[(size_t)n * 8 + 4] = ev[4] * inv;
        *(float4*)(g_xs8 + (size_t)n * 8) = make_float4(ps[0], ps[1], ps[2], ps[3]);
        g_xs8[(size_t)n * 8 + 4] = ps[4];
    }
    if (ok && h == 1) {
        *(float4*)(g_xd8 + (size_t)n * 8) = make_float4(pd[0], pd[1], pd[2], pd[3]);
        g_xd8[(size_t)n * 8 + 4] = pd[4];
        // re-zero this node's B4 accumulator for the upcoming k_edge pass
        *(float4*)(g_B4 + (size_t)n * 4) = make_float4(0.f, 0.f, 0.f, 0.f);
    }

    // topology features + hidden layer
    int nc = (n < N) ? n : (N - 1);
    float deg   = (float)__ldg(&g_deg[nc]);
    float dmaxf = (float)g_degmax;
    float meanf = Ef / (float)N;
    unsigned kk0 = h ? KEY2.a : KEY1.a;
    unsigned kk1 = h ? KEY2.b : KEY1.b;
    float u_own   = jax_uniform01(kk0, kk1, (unsigned)n);
    float u_other = __shfl_xor_sync(0xffffffffu, u_own, 1);
    float u1 = h ? u_other : u_own;   // KEY1 stream
    float u2 = h ? u_own   : u_other; // KEY2 stream

    float tv[5];
    tv[0] = deg / (dmaxf + 1e-6f);
    tv[1] = u1 * 0.5f + 0.25f;
    tv[2] = deg / (Ef + 1e-6f);
    tv[3] = 1.0f / (1.0f + __expf(-(deg - meanf)));
    tv[4] = u2;

    if (ok) {
        float4* hout = (float4*)(g_h + (size_t)n * HH);
#pragma unroll
        for (int jc = 0; jc < 8; jc++) {
            int jc4 = h * 8 + jc;
            float4 hv = s_t1b4[jc4];
#pragma unroll
            for (int i = 0; i < AA; i++) {
                float4 wv = s_t1wT[i * 16 + jc4];
                hv.x += tv[i] * wv.x; hv.y += tv[i] * wv.y;
                hv.z += tv[i] * wv.z; hv.w += tv[i] * wv.w;
            }
            hv.x = fmaxf(hv.x, 0.f); hv.y = fmaxf(hv.y, 0.f);
            hv.z = fmaxf(hv.z, 0.f); hv.w = fmaxf(hv.w, 0.f);
            hout[jc4] = hv;
        }
    }
}

// ---------------- K3: edge kernel — thread-per-edge softmax, f32x2 store -----
__global__ void __launch_bounds__(256)
k_edge(const void* __restrict__ ei, long long E,
       const float* __restrict__ anchor, float* __restrict__ outE) {
    __shared__ unsigned long long s_bp[5][256];   // packed (b,b), column-major
    int tid  = threadIdx.x;
    int lane = tid & 31;
    int warp = tid >> 5;
    int is64 = detect_is64(ei);

    unsigned long long alo[AA], ahi[AA];
#pragma unroll
    for (int k = 0; k < AA; k++) {
        float4 a = __ldg(((const float4*)anchor) + k * 32 + lane);
        alo[k] = packf2(a.x, a.y);
        ahi[k] = packf2(a.z, a.w);
    }

    long long e = (long long)blockIdx.x * 256 + tid;
    if (e < E) {
        int src = ld_edge(ei, e, is64);
        int dst = ld_edge(ei, E + e, is64);
        float4 s4 = __ldg((const float4*)(g_xs8 + (size_t)src * 8));
        float  s5 = __ldg(g_xs8 + (size_t)src * 8 + 4);
        float4 d4 = __ldg((const float4*)(g_xd8 + (size_t)dst * 8));
        float  d5 = __ldg(g_xd8 + (size_t)dst * 8 + 4);
        float l[5];
        l[0] = s4.x + d4.x; l[1] = s4.y + d4.y; l[2] = s4.z + d4.z;
        l[3] = s4.w + d4.w; l[4] = s5 + d5;
#pragma unroll
        for (int k = 0; k < 5; k++) l[k] = fmaxf(l[k], 0.01f * l[k]); // leaky
        float m = l[0];
#pragma unroll
        for (int k = 1; k < 5; k++) m = fmaxf(m, l[k]);
        float ev[5], sum = 0.f;
#pragma unroll
        for (int k = 0; k < 5; k++) { ev[k] = __expf(l[k] - m); sum += ev[k]; }
        float inv = __fdividef(1.0f, sum);
        float b[5];
#pragma unroll
        for (int k = 0; k < 5; k++) b[k] = ev[k] * inv;
        red_add_v4(g_B4 + (size_t)src * 4, b[0], b[1], b[2], b[3]);
#pragma unroll
        for (int k = 0; k < 5; k++) s_bp[k][tid] = pack2(b[k]);  // conflict-free
    }
    __syncwarp();

    long long base = (long long)blockIdx.x * 256 + warp * 32;
    float4* o4 = (float4*)outE;
    int nfull = (base + 32 <= E) ? 32 : (int)(E > base ? E - base : 0);
    if (nfull == 32) {
#pragma unroll 4
        for (int j = 0; j < 32; j++) {
            int sb = warp * 32 + j;                    // uniform -> broadcast
            unsigned long long p0 = s_bp[0][sb], p1 = s_bp[1][sb],
                               p2 = s_bp[2][sb], p3 = s_bp[3][sb],
                               p4 = s_bp[4][sb];
            unsigned long long lo = mul2(p0, alo[0]);
            lo = fma2(p1, alo[1], lo); lo = fma2(p2, alo[2], lo);
            lo = fma2(p3, alo[3], lo); lo = fma2(p4, alo[4], lo);
            unsigned long long hi = mul2(p0, ahi[0]);
            hi = fma2(p1, ahi[1], hi); hi = fma2(p2, ahi[2], hi);
            hi = fma2(p3, ahi[3], hi); hi = fma2(p4, ahi[4], hi);
            float4 o;
            unpack2(lo, o.x, o.y);
            unpack2(hi, o.z, o.w);
            __stcs(o4 + (size_t)(base + j) * 32 + lane, o);
        }
    } else {
        for (int j = 0; j < nfull; j++) {
            int sb = warp * 32 + j;
            unsigned long long p0 = s_bp[0][sb], p1 = s_bp[1][sb],
                               p2 = s_bp[2][sb], p3 = s_bp[3][sb],
                               p4 = s_bp[4][sb];
            unsigned long long lo = mul2(p0, alo[0]);
            lo = fma2(p1, alo[1], lo); lo = fma2(p2, alo[2], lo);
            lo = fma2(p3, alo[3], lo); lo = fma2(p4, alo[4], lo);
            unsigned long long hi = mul2(p0, ahi[0]);
            hi = fma2(p1, ahi[1], hi); hi = fma2(p2, ahi[2], hi);
            hi = fma2(p3, ahi[3], hi); hi = fma2(p4, ahi[4], hi);
            float4 o;
            unpack2(lo, o.x, o.y);
            unpack2(hi, o.z, o.w);
            __stcs(o4 + (size_t)(base + j) * 32 + lane, o);
        }
    }
}

// ---------------- K4: final per-node (smem-staged, 2 cols/lane j-split) ------
// Warp = (jh = w>>2, ch = (w>>1)&1, nh = w&1); lane owns cols ch*64+lane and
// ch*64+lane+32. Each h broadcast read feeds TWO column outputs -> compute
// LDS halved vs 1 col/lane. 2 blocks/SM (128 regs), grid 296 = single wave.
__global__ void __launch_bounds__(256, 2)
k_final(const float* __restrict__ x,
        const float* __restrict__ node_anchor, const float* __restrict__ anchor,
        const float* __restrict__ t2w, const float* __restrict__ t2b,
        float* __restrict__ outF, int N) {
    __shared__ float4 s_h4[32 * 16];    // 32 nodes x 64 floats (8 KB)
    __shared__ float  s_xt[32 * DD];    // 32 nodes x 128 floats (16 KB)
    __shared__ float  s_accA[32 * DD];  // jh=0 partials (16 KB)
    __shared__ float  s_accB[32 * DD];  // jh=1 partials (16 KB)
    __shared__ float4 s_B[32];
    __shared__ float4 s_aw[32];
    __shared__ float  s_aw5[32];
    __shared__ float  s_degf[32];

    int tid  = threadIdx.x;
    int lane = tid & 31;
    int warp = tid >> 5;
    int jh   = warp >> 2;          // j-half
    int ch   = (warp >> 1) & 1;    // column-half
    int nh   = warp & 1;           // node-half (compute phase)
    int col0 = ch * 64 + lane;
    int col1 = col0 + 32;

    // jh-half of t2_w rows for col0 and col1, packed f32x2 pairs
    unsigned long long wpA[16], wpB[16];
#pragma unroll
    for (int j4 = 0; j4 < 8; j4++) {
        float4 wv = ((const float4*)t2w)[(size_t)col0 * 16 + jh * 8 + j4];
        wpA[2*j4+0] = packf2(wv.x, wv.y);
        wpA[2*j4+1] = packf2(wv.z, wv.w);
        float4 wu = ((const float4*)t2w)[(size_t)col1 * 16 + jh * 8 + j4];
        wpB[2*j4+0] = packf2(wu.x, wu.y);
        wpB[2*j4+1] = packf2(wu.z, wu.w);
    }
    float areg0[AA], nareg0[AA], areg1[AA], nareg1[AA];
#pragma unroll
    for (int k = 0; k < AA; k++) {
        areg0[k]  = __ldg(&anchor[k * DD + col0]);
        nareg0[k] = __ldg(&node_anchor[k * DD + col0]);
        areg1[k]  = __ldg(&anchor[k * DD + col1]);
        nareg1[k] = __ldg(&node_anchor[k * DD + col1]);
    }
    float bias0 = __ldg(&t2b[col0]);
    float bias1 = __ldg(&t2b[col1]);
    float* s_out = jh ? s_accB : s_accA;

    int ntiles = (N + 31) >> 5;
    for (int tile = blockIdx.x; tile < ntiles; tile += gridDim.x) {
        int nb = tile << 5;
        __syncthreads();                 // protect smem reuse across tiles
        // ---- stage 32 h rows + 32 x rows, coalesced, deep MLP ----
#pragma unroll
        for (int k = 0; k < 2; k++) {
            int idx = k * 256 + tid;
            int row = idx >> 4, c = idx & 15;
            int gn = nb + row;
            float4 v = make_float4(0.f, 0.f, 0.f, 0.f);
            if (gn < N) v = __ldg(((const float4*)g_h) + (size_t)gn * 16 + c);
            s_h4[idx] = v;
        }
#pragma unroll
        for (int k = 0; k < 4; k++) {
            int idx = k * 256 + tid;
            int row = idx >> 5, c = idx & 31;
            int gn = nb + row;
            float4 v = make_float4(0.f, 0.f, 0.f, 0.f);
            if (gn < N) v = __ldg(((const float4*)x) + (size_t)gn * 32 + c);
            *(float4*)(s_xt + row * DD + c * 4) = v;
        }
        if (tid < 32) {
            int gn = nb + tid;
            if (gn < N) {
                s_B[tid]    = *(const float4*)(g_B4 + (size_t)gn * 4);
                s_aw[tid]   = *(const float4*)(g_aw8 + (size_t)gn * 8);
                s_aw5[tid]  = g_aw8[(size_t)gn * 8 + 4];
                s_degf[tid] = (float)g_deg[gn];
                g_deg[gn]   = 0;   // re-zero for next graph replay
            }
        }
        __syncthreads();
        // ---- compute: warp does its j-half, node-half, for 2 cols/lane ----
#pragma unroll 2
        for (int j = 0; j < 16; j++) {
            int nl = nh * 16 + j;
            const ulonglong2* hrow =
                (const ulonglong2*)(s_h4 + nl * 16) + jh * 8;
            unsigned long long a0 = 0ULL, a1 = 0ULL;   // col0 chains
            unsigned long long b0 = 0ULL, b1 = 0ULL;   // col1 chains
#pragma unroll
            for (int q = 0; q < 2; q++) {               // broadcast LDS.128
                ulonglong2 hA = hrow[q*4+0], hB = hrow[q*4+1],
                           hC = hrow[q*4+2], hD = hrow[q*4+3];
                a0 = fma2(hA.x, wpA[8*q+0], a0); b0 = fma2(hA.x, wpB[8*q+0], b0);
                a1 = fma2(hA.y, wpA[8*q+1], a1); b1 = fma2(hA.y, wpB[8*q+1], b1);
                a0 = fma2(hB.x, wpA[8*q+2], a0); b0 = fma2(hB.x, wpB[8*q+2], b0);
                a1 = fma2(hB.y, wpA[8*q+3], a1); b1 = fma2(hB.y, wpB[8*q+3], b1);
                a0 = fma2(hC.x, wpA[8*q+4], a0); b0 = fma2(hC.x, wpB[8*q+4], b0);
                a1 = fma2(hC.y, wpA[8*q+5], a1); b1 = fma2(hC.y, wpB[8*q+5], b1);
                a0 = fma2(hD.x, wpA[8*q+6], a0); b0 = fma2(hD.x, wpB[8*q+6], b0);
                a1 = fma2(hD.y, wpA[8*q+7], a1); b1 = fma2(hD.y, wpB[8*q+7], b1);
            }
            a0 = fma2(a1, pack2(1.0f), a0);
            b0 = fma2(b1, pack2(1.0f), b0);
            float s0, s1, t0, t1;
            unpack2(a0, s0, s1);
            unpack2(b0, t0, t1);
            s_out[nl * DD + col0] = s0 + s1;   // conflict-free STS
            s_out[nl * DD + col1] = t0 + t1;
        }
        __syncthreads();
        // ---- finalize: warp handles nodes nh*16+jh*8+j, its 2 cols ----
#pragma unroll 2
        for (int j = 0; j < 8; j++) {
            int nl = nh * 16 + jh * 8 + j;
            int gn = nb + nl;
            if (gn >= N) continue;
            float4 B   = s_B[nl];                       // broadcast LDS
            float deg  = s_degf[nl];
            float4 aw4 = s_aw[nl];
            float aw5  = s_aw5[nl];
            float B4v  = deg - B.x - B.y - B.z - B.w;

            float xv0  = s_xt[nl * DD + col0];
            float acc0 = bias0 + s_accA[nl * DD + col0] + s_accB[nl * DD + col0];
            float agg0 = B.x*areg0[0] + B.y*areg0[1] + B.z*areg0[2]
                       + B.w*areg0[3] + B4v*areg0[4];
            float np0  = aw4.x*nareg0[0] + aw4.y*nareg0[1] + aw4.z*nareg0[2]
                       + aw4.w*nareg0[3] + aw5*nareg0[4];
            outF[(size_t)gn * DD + col0] = xv0 + np0 + acc0 * agg0;

            float xv1  = s_xt[nl * DD + col1];
            float acc1 = bias1 + s_accA[nl * DD + col1] + s_accB[nl * DD + col1];
            float agg1 = B.x*areg1[0] + B.y*areg1[1] + B.z*areg1[2]
                       + B.w*areg1[3] + B4v*areg1[4];
            float np1  = aw4.x*nareg1[0] + aw4.y*nareg1[1] + aw4.z*nareg1[2]
                       + aw4.w*nareg1[3] + aw5*nareg1[4];
            outF[(size_t)gn * DD + col1] = xv1 + np1 + acc1 * agg1;
        }
    }
}

// ---------------- launch ------------------------------------------------------
extern "C" void kernel_launch(void* const* d_in, const int* in_sizes, int n_in,
                              void* d_out, int out_size) {
    const float* x           = (const float*)d_in[0];
    const void*  ei          = d_in[1];
    const float* anchor      = (const float*)d_in[3];
    const float* w_w         = (const float*)d_in[4];
    const float* w_b         = (const float*)d_in[5];
    const float* node_anchor = (const float*)d_in[6];
    const float* attn_w      = (const float*)d_in[7];
    const float* attn_b      = (const float*)d_in[8];
    const float* t1w         = (const float*)d_in[9];
    const float* t1b         = (const float*)d_in[10];
    const float* t2w         = (const float*)d_in[11];
    const float* t2b         = (const float*)d_in[12];

    int       N  = in_sizes[0] / DD;
    long long E  = (long long)in_sizes[1] / 2;
    float     Ef = (float)E;

    float* outF = (float*)d_out;                  // final_x [N, D]
    float* outE = outF + (size_t)N * DD;          // edge_prompt [E, D]

    k_degree<<<(unsigned)((E + 255) / 256), 256>>>(ei, E);
    k_nodeA <<<(N + BN - 1) / BN, NT>>>(x, attn_w, attn_b, w_w, w_b,
                                        t1w, t1b, N, Ef);
    k_edge  <<<(unsigned)((E + 255) / 256), 256>>>(ei, E, anchor, outE);
    k_final <<<296, 256>>>(x, node_anchor, anchor, t2w, t2b, outF, N);
}